// round 6
// baseline (speedup 1.0000x reference)
#include <cuda_runtime.h>
#include <cuda_bf16.h>
#include <math.h>

// Problem constants
#define B_  256
#define T_  512
#define I_  128
#define H_  512
#define O_  64
#define ALPHA 0.2f
#define BETA_ 8.0f
#define THRESH 20.0f

// Recurrence decomposition
#define NBG 16      // batch groups
#define BB  16      // batches per group
#define NCT 2       // column tiles
#define CTW 256     // columns per tile
#define NKS 4       // k splits
#define KSW 128     // k per split
#define HPAD 20     // padded row (floats) for hs[k][b] — 16B-aligned, conflict-spread

// Scratch (device globals; no runtime allocation)
__device__ float g_xw[(size_t)B_ * T_ * H_];       // xw (+b_h), pristine through recurrence
__device__ float g_h [(size_t)B_ * T_ * H_];       // h states for readout
__device__ float g_WhhT[H_ * H_];                  // W_hh^T  [k][j]
__device__ float g_WxhT[I_ * H_];                  // W_xh^T  [i][h]
__device__ float g_WoutT[H_ * O_];                 // W_out^T [k][o]
__device__ float g_part[(size_t)NBG * NKS * BB * H_];  // per-step partial sums (2 MB)
__device__ int   g_cnt[NBG];                       // group barrier counters

// ---------------------------------------------------------------------------
__global__ void zero_cnt_kernel() {
    if (threadIdx.x < NBG) g_cnt[threadIdx.x] = 0;
}

// ---------------------------------------------------------------------------
__global__ void transpose_kernel(const float* __restrict__ in, float* __restrict__ out,
                                 int R, int C) {
    int idx = blockIdx.x * blockDim.x + threadIdx.x;
    if (idx < R * C) {
        int r = idx / C;
        int c = idx % C;
        out[c * R + r] = in[idx];
    }
}

// ---------------------------------------------------------------------------
// Tiled SGEMM: C[M,N] = A[M,K] * B[K,N] (+ bias[N]); 64x64 tile, BK=32.
// ---------------------------------------------------------------------------
__global__ __launch_bounds__(256) void sgemm64(const float* __restrict__ A,
                                               const float* __restrict__ Bm,
                                               const float* __restrict__ bias,
                                               float* __restrict__ C,
                                               int M, int N, int K) {
    __shared__ float As[32][65];
    __shared__ float Bs[32][64];

    int tid = threadIdx.x;
    int m0 = blockIdx.x * 64;
    int n0 = blockIdx.y * 64;
    int tx = tid % 16;
    int ty = tid / 16;

    int a_k = tid % 32;
    int a_m = tid / 32;
    int b_n = tid % 64;
    int b_k = tid / 64;

    float acc[4][4];
#pragma unroll
    for (int i = 0; i < 4; i++)
#pragma unroll
        for (int j = 0; j < 4; j++) acc[i][j] = 0.0f;

    for (int k0 = 0; k0 < K; k0 += 32) {
#pragma unroll
        for (int i = 0; i < 8; i++)
            As[a_k][a_m + 8 * i] = A[(size_t)(m0 + a_m + 8 * i) * K + (k0 + a_k)];
#pragma unroll
        for (int i = 0; i < 8; i++)
            Bs[b_k + 4 * i][b_n] = Bm[(size_t)(k0 + b_k + 4 * i) * N + (n0 + b_n)];
        __syncthreads();

#pragma unroll
        for (int kk = 0; kk < 32; kk++) {
            float a[4], b[4];
#pragma unroll
            for (int i = 0; i < 4; i++) a[i] = As[kk][ty * 4 + i];
#pragma unroll
            for (int j = 0; j < 4; j++) b[j] = Bs[kk][tx * 4 + j];
#pragma unroll
            for (int i = 0; i < 4; i++)
#pragma unroll
                for (int j = 0; j < 4; j++) acc[i][j] += a[i] * b[j];
        }
        __syncthreads();
    }

#pragma unroll
    for (int i = 0; i < 4; i++) {
        size_t row = (size_t)(m0 + ty * 4 + i);
#pragma unroll
        for (int j = 0; j < 4; j++) {
            int col = n0 + tx * 4 + j;
            float v = acc[i][j];
            if (bias) v += bias[col];
            C[row * N + col] = v;
        }
    }
}

// ---------------------------------------------------------------------------
__device__ __forceinline__ float phi_fn(float x) {
    float z = BETA_ * x;
    if (z > THRESH) return x;
    return log1pf(expf(z)) * (1.0f / BETA_);
}

// ---------------------------------------------------------------------------
// Recurrence v2: 128 blocks = 16 batch-groups x 2 col-tiles x 4 k-splits.
// Block: 256 threads, full h (16 batches) in SMEM, partial matvec over its
// (col-tile, k-split); group barrier; fused redundant reduce + activation.
// ---------------------------------------------------------------------------
__global__ __launch_bounds__(256) void recurrence2_kernel() {
    const float* __restrict__ WhhT = g_WhhT;
    const float* __restrict__ xw   = g_xw;
    float* __restrict__ hout = g_h;
    float* __restrict__ part = g_part;

    const int tid   = threadIdx.x;
    const int bid   = blockIdx.x;
    const int bg    = bid >> 3;      // 0..15
    const int lrank = bid & 7;       // 0..7
    const int ct    = lrank >> 2;    // 0..1
    const int ks    = lrank & 3;     // 0..3

    __shared__ float hs[H_][HPAD];   // h_{t-1}: [k][b], padded row (40 KB)

    for (int i = tid; i < H_; i += 256) {
#pragma unroll
        for (int b = 0; b < BB; b++) hs[i][b] = 0.0f;
    }

    // h_old kept in registers for the units this thread owns in the reduce
    float hold[8][4];
#pragma unroll
    for (int q = 0; q < 8; q++)
#pragma unroll
        for (int i = 0; i < 4; i++) hold[q][i] = 0.0f;

    __syncthreads();

    const int j = ct * CTW + tid;                               // column owned in compute
    const float* wcol = WhhT + (size_t)(ks * KSW) * H_ + j;     // W^T[k][j], k in split
    float* pwr       = part + ((size_t)(bg * NKS + ks) * BB) * H_ + j;
    const float* prd = part + ((size_t)bg * NKS) * BB * H_;
    volatile int* cntp = &g_cnt[bg];

    for (int t = 0; t < T_; t++) {
        // ---- partial matvec: acc[b] = sum_{k in split} h[b][k] * W^T[k][j] ----
        float acc[BB];
#pragma unroll
        for (int b = 0; b < BB; b++) acc[b] = 0.0f;

        const float* wp = wcol;
#pragma unroll 4
        for (int kk = 0; kk < KSW; kk++) {
            const int k = ks * KSW + kk;
            float w = wp[0]; wp += H_;                           // coalesced, L1-resident
            float4 h0 = *(const float4*)&hs[k][0];               // warp broadcast
            float4 h1 = *(const float4*)&hs[k][4];
            float4 h2 = *(const float4*)&hs[k][8];
            float4 h3 = *(const float4*)&hs[k][12];
            acc[0]  += h0.x * w; acc[1]  += h0.y * w; acc[2]  += h0.z * w; acc[3]  += h0.w * w;
            acc[4]  += h1.x * w; acc[5]  += h1.y * w; acc[6]  += h1.z * w; acc[7]  += h1.w * w;
            acc[8]  += h2.x * w; acc[9]  += h2.y * w; acc[10] += h2.z * w; acc[11] += h2.w * w;
            acc[12] += h3.x * w; acc[13] += h3.y * w; acc[14] += h3.z * w; acc[15] += h3.w * w;
        }

#pragma unroll
        for (int b = 0; b < BB; b++) pwr[(size_t)b * H_] = acc[b];

        // ---- group barrier (8 blocks), monotonic counter ----
        __syncthreads();
        if (tid == 0) {
            __threadfence();
            atomicAdd(&g_cnt[bg], 1);
            const int target = 8 * (t + 1);
            while (*cntp < target) __nanosleep(32);
        }
        __syncthreads();

        // ---- fused reduce + activation (every block computes full h for its bg) ----
        // unit u = q*256 + tid -> (jr = u & 511, batches b0..b0+3 with b0 = (u>>9)<<2)
#pragma unroll
        for (int q = 0; q < 8; q++) {
            const int u  = q * 256 + tid;
            const int jr = u & (H_ - 1);
            const int b0 = (u >> 9) << 2;

            float s[4];
#pragma unroll
            for (int i = 0; i < 4; i++) {
                const int b = b0 + i;
                float v = xw[((size_t)(bg * BB + b) * T_ + t) * H_ + jr];   // includes b_h
#pragma unroll
                for (int r = 0; r < NKS; r++)
                    v += __ldcg(&prd[((size_t)(r * BB + b)) * H_ + jr]);
                s[i] = v;
            }

            float hn[4];
#pragma unroll
            for (int i = 0; i < 4; i++) {
                hn[i] = (1.0f - ALPHA) * hold[q][i] + ALPHA * phi_fn(s[i]);
                hold[q][i] = hn[i];
            }

            // publish h_t to SMEM for next step's compute phase (aligned float4)
            *(float4*)&hs[jr][b0] = make_float4(hn[0], hn[1], hn[2], hn[3]);

            // exactly one block per bg writes each unit to global h
            if (q == lrank) {
#pragma unroll
                for (int i = 0; i < 4; i++)
                    hout[((size_t)(bg * BB + b0 + i) * T_ + t) * H_ + jr] = hn[i];
            }
        }
        __syncthreads();
    }
}

// ---------------------------------------------------------------------------
// kernel_launch
// inputs: x[B,T,I], W_xh[H,I], W_hh[H,H], b_h[H], W_out[O,H], b_out[O]
// output: float [B,T,O]
// ---------------------------------------------------------------------------
extern "C" void kernel_launch(void* const* d_in, const int* in_sizes, int n_in,
                              void* d_out, int out_size) {
    const float* x     = (const float*)d_in[0];
    const float* W_xh  = (const float*)d_in[1];
    const float* W_hh  = (const float*)d_in[2];
    const float* b_h   = (const float*)d_in[3];
    const float* W_out = (const float*)d_in[4];
    const float* b_out = (const float*)d_in[5];
    float* out = (float*)d_out;

    float *xw_p, *h_p, *whhT_p, *wxhT_p, *woutT_p;
    cudaGetSymbolAddress((void**)&xw_p,    g_xw);
    cudaGetSymbolAddress((void**)&h_p,     g_h);
    cudaGetSymbolAddress((void**)&whhT_p,  g_WhhT);
    cudaGetSymbolAddress((void**)&wxhT_p,  g_WxhT);
    cudaGetSymbolAddress((void**)&woutT_p, g_WoutT);

    // 1) transposes + counter reset
    transpose_kernel<<<(H_ * I_ + 255) / 256, 256>>>(W_xh, wxhT_p, H_, I_);
    transpose_kernel<<<(H_ * H_ + 255) / 256, 256>>>(W_hh, whhT_p, H_, H_);
    transpose_kernel<<<(O_ * H_ + 255) / 256, 256>>>(W_out, woutT_p, O_, H_);
    zero_cnt_kernel<<<1, 32>>>();

    // 2) xw = x @ W_xh^T + b_h -> g_xw  [B*T, H]
    {
        dim3 grid((B_ * T_) / 64, H_ / 64);
        sgemm64<<<grid, 256>>>(x, wxhT_p, b_h, xw_p, B_ * T_, H_, I_);
    }

    // 3) recurrence: g_xw (pristine) -> g_h
    recurrence2_kernel<<<NBG * NCT * NKS, 256>>>();

    // 4) y = h @ W_out^T + b_out -> d_out [B*T, O]
    {
        dim3 grid((B_ * T_) / 64, O_ / 64);
        sgemm64<<<grid, 256>>>(h_p, woutT_p, b_out, out, B_ * T_, O_, H_);
    }
}

// round 10
// speedup vs baseline: 1.2466x; 1.2466x over previous
#include <cuda_runtime.h>
#include <cuda_bf16.h>
#include <math.h>
#include <stdint.h>

// Problem constants
#define B_  256
#define T_  512
#define I_  128
#define H_  512
#define O_  64
#define ALPHA 0.2f
#define BETA_ 8.0f
#define THRESH 20.0f

// Recurrence decomposition: 16 clusters x 8 CTAs. CTA owns 64 cols, cluster owns 16 batches.
#define CLN   8          // CTAs per cluster
#define COLS_ 64         // columns per CTA
#define BB    16         // batches per cluster (batch group)
#define THR   128        // threads per CTA: 64 cols x 2 batch-quads(8)
#define HPAD  20         // padded floats per h row (16B aligned, conflict-spread)
#define HBUF  (H_ * HPAD)            // one h buffer in floats (10240)
#define WS_FLOATS (H_ * COLS_)       // 32768 floats = 128KB
#define SMEMB ((WS_FLOATS + 2 * HBUF) * 4)   // 212992 bytes

// Scratch (device globals; no runtime allocation)
__device__ float g_xw[(size_t)B_ * T_ * H_];   // xw (+b_h)
__device__ float g_h [(size_t)B_ * T_ * H_];   // h states for readout
__device__ float g_WhhT[H_ * H_];              // W_hh^T  [k][j]
__device__ float g_WxhT[I_ * H_];              // W_xh^T  [i][h]
__device__ float g_WoutT[H_ * O_];             // W_out^T [k][o]

// ---------------------------------------------------------------------------
__global__ void transpose_kernel(const float* __restrict__ in, float* __restrict__ out,
                                 int R, int C) {
    int idx = blockIdx.x * blockDim.x + threadIdx.x;
    if (idx < R * C) {
        int r = idx / C;
        int c = idx % C;
        out[c * R + r] = in[idx];
    }
}

// ---------------------------------------------------------------------------
// Tiled SGEMM: C[M,N] = A[M,K] * B[K,N] (+ bias[N]); 64x64 tile, BK=32.
// ---------------------------------------------------------------------------
__global__ __launch_bounds__(256) void sgemm64(const float* __restrict__ A,
                                               const float* __restrict__ Bm,
                                               const float* __restrict__ bias,
                                               float* __restrict__ C,
                                               int M, int N, int K) {
    __shared__ float As[32][65];
    __shared__ float Bs[32][64];

    int tid = threadIdx.x;
    int m0 = blockIdx.x * 64;
    int n0 = blockIdx.y * 64;
    int tx = tid % 16;
    int ty = tid / 16;

    int a_k = tid % 32;
    int a_m = tid / 32;
    int b_n = tid % 64;
    int b_k = tid / 64;

    float acc[4][4];
#pragma unroll
    for (int i = 0; i < 4; i++)
#pragma unroll
        for (int j = 0; j < 4; j++) acc[i][j] = 0.0f;

    for (int k0 = 0; k0 < K; k0 += 32) {
#pragma unroll
        for (int i = 0; i < 8; i++)
            As[a_k][a_m + 8 * i] = A[(size_t)(m0 + a_m + 8 * i) * K + (k0 + a_k)];
#pragma unroll
        for (int i = 0; i < 8; i++)
            Bs[b_k + 4 * i][b_n] = Bm[(size_t)(k0 + b_k + 4 * i) * N + (n0 + b_n)];
        __syncthreads();

#pragma unroll
        for (int kk = 0; kk < 32; kk++) {
            float a[4], b[4];
#pragma unroll
            for (int i = 0; i < 4; i++) a[i] = As[kk][ty * 4 + i];
#pragma unroll
            for (int j = 0; j < 4; j++) b[j] = Bs[kk][tx * 4 + j];
#pragma unroll
            for (int i = 0; i < 4; i++)
#pragma unroll
                for (int j = 0; j < 4; j++) acc[i][j] += a[i] * b[j];
        }
        __syncthreads();
    }

#pragma unroll
    for (int i = 0; i < 4; i++) {
        size_t row = (size_t)(m0 + ty * 4 + i);
#pragma unroll
        for (int j = 0; j < 4; j++) {
            int col = n0 + tx * 4 + j;
            float v = acc[i][j];
            if (bias) v += bias[col];
            C[row * N + col] = v;
        }
    }
}

// ---------------------------------------------------------------------------
__device__ __forceinline__ float phi_fn(float x) {
    float z = BETA_ * x;
    if (z > THRESH) return x;
    return log1pf(expf(z)) * (1.0f / BETA_);
}

__device__ __forceinline__ uint32_t smem_u32(const void* p) {
    uint32_t a;
    asm("{ .reg .u64 t; cvta.to.shared.u64 t, %1; cvt.u32.u64 %0, t; }" : "=r"(a) : "l"(p));
    return a;
}

__device__ __forceinline__ unsigned long long pack2(float lo, float hi) {
    unsigned long long r;
    asm("mov.b64 %0, {%1, %2};" : "=l"(r) : "r"(__float_as_uint(lo)), "r"(__float_as_uint(hi)));
    return r;
}

__device__ __forceinline__ void unpack2(unsigned long long v, float& lo, float& hi) {
    uint32_t a, b;
    asm("mov.b64 {%0, %1}, %2;" : "=r"(a), "=r"(b) : "l"(v));
    lo = __uint_as_float(a);
    hi = __uint_as_float(b);
}

__device__ __forceinline__ void fma2(unsigned long long& acc, unsigned long long h,
                                     unsigned long long w) {
    asm("fma.rn.f32x2 %0, %1, %2, %0;" : "+l"(acc) : "l"(h), "l"(w));
}

// Remote (or self) SMEM v4 store within the cluster.
__device__ __forceinline__ void st_cluster_v4(uint32_t laddr, int rank,
                                              float a, float b, float c, float d) {
    asm volatile(
        "{ .reg .u32 ra;\n\t"
        "mapa.shared::cluster.u32 ra, %0, %1;\n\t"
        "st.shared::cluster.v4.f32 [ra], {%2, %3, %4, %5}; }"
        :: "r"(laddr), "r"(rank), "f"(a), "f"(b), "f"(c), "f"(d) : "memory");
}

// ---------------------------------------------------------------------------
// Recurrence v3: clusters of 8 CTAs, DSMEM h exchange, cluster barrier per step.
// CTA rank r owns columns [64r, 64r+64); thread t: col jl = t%64, batches 8*(t/64)..+7.
// W slice (512x64, 128KB) in SMEM; h double-buffered in SMEM (padded rows).
// ---------------------------------------------------------------------------
__global__ __launch_bounds__(THR, 1) __cluster_dims__(CLN, 1, 1)
void recurrence3_kernel() {
    extern __shared__ float smem[];
    float* Ws = smem;                 // [k][jl]  stride 64
    float* hb = smem + WS_FLOATS;     // [p][k][b] stride HPAD, two buffers

    const int tid = threadIdx.x;
    uint32_t rank;
    asm("mov.u32 %0, %%cluster_ctarank;" : "=r"(rank));
    const int bg = blockIdx.x / CLN;          // batch group 0..15
    const int jl = tid & (COLS_ - 1);         // 0..63
    const int bq = tid >> 6;                  // 0..1
    const int jg = (int)rank * COLS_ + jl;    // global hidden unit 0..511
    const int bbase = bg * BB + bq * 8;       // first of this thread's 8 batches

    // ---- preload W slice into SMEM: Ws[k*64 + jl] = W^T[k][jg] ----
    {
        const float* __restrict__ WhhT = g_WhhT;
        const int j0 = (int)rank * COLS_;
        for (int idx = tid; idx < WS_FLOATS; idx += THR) {
            int k = idx >> 6;
            int c = idx & 63;
            Ws[idx] = WhhT[k * H_ + j0 + c];
        }
    }
    // ---- zero h buffer 0 ----
    for (int idx = tid; idx < HBUF; idx += THR) hb[idx] = 0.0f;
    __syncthreads();
    asm volatile("barrier.cluster.arrive.aligned;" ::: "memory");
    asm volatile("barrier.cluster.wait.aligned;" ::: "memory");

    const float* __restrict__ xwb = g_xw + (size_t)bbase * T_ * H_ + jg;
    float*       __restrict__ hob = g_h  + (size_t)bbase * T_ * H_ + jg;

    float hold[8];
#pragma unroll
    for (int i = 0; i < 8; i++) hold[i] = 0.0f;

    int p = 0;
    const uint32_t hb_base = smem_u32(hb);

    for (int t = 0; t < T_; t++) {
        // prefetch xw for this step (streaming)
        float xv[8];
#pragma unroll
        for (int i = 0; i < 8; i++)
            xv[i] = __ldcs(xwb + ((size_t)i * T_ + t) * H_);

        unsigned long long a0 = pack2(xv[0], xv[1]);
        unsigned long long a1 = pack2(xv[2], xv[3]);
        unsigned long long a2 = pack2(xv[4], xv[5]);
        unsigned long long a3 = pack2(xv[6], xv[7]);

        const float* __restrict__ wp = Ws + jl;
        const float* __restrict__ hp = hb + p * HBUF + bq * 8;

#pragma unroll 8
        for (int k = 0; k < H_; k++) {
            float w = wp[k * COLS_];
            unsigned long long w2;
            asm("mov.b64 %0, {%1, %1};" : "=l"(w2) : "r"(__float_as_uint(w)));
            const ulonglong2* hv = reinterpret_cast<const ulonglong2*>(hp + k * HPAD);
            ulonglong2 hA = hv[0];   // batches 0..3 of this thread's 8
            ulonglong2 hB = hv[1];   // batches 4..7
            fma2(a0, hA.x, w2);
            fma2(a1, hA.y, w2);
            fma2(a2, hB.x, w2);
            fma2(a3, hB.y, w2);
        }

        // activation + leak
        float s[8];
        unpack2(a0, s[0], s[1]);
        unpack2(a1, s[2], s[3]);
        unpack2(a2, s[4], s[5]);
        unpack2(a3, s[6], s[7]);
        float hn[8];
#pragma unroll
        for (int i = 0; i < 8; i++) {
            hn[i] = (1.0f - ALPHA) * hold[i] + ALPHA * phi_fn(s[i]);
            hold[i] = hn[i];
        }

        // exchange: write h_t[jg][b0..b7] into every CTA's next buffer
        const int p2 = p ^ 1;
        const uint32_t la = hb_base + (uint32_t)(p2 * HBUF + jg * HPAD + bq * 8) * 4u;
#pragma unroll
        for (int c = 0; c < CLN; c++) {
            st_cluster_v4(la,       c, hn[0], hn[1], hn[2], hn[3]);
            st_cluster_v4(la + 16u, c, hn[4], hn[5], hn[6], hn[7]);
        }

        // stash h_t to global for the readout GEMM (coalesced per batch)
#pragma unroll
        for (int i = 0; i < 8; i++)
            hob[((size_t)i * T_ + t) * H_] = hn[i];

        // cluster barrier: all exchange writes visible, all reads of buffer p done
        asm volatile("barrier.cluster.arrive.aligned;" ::: "memory");
        asm volatile("barrier.cluster.wait.aligned;" ::: "memory");
        p = p2;
    }
}

// ---------------------------------------------------------------------------
// kernel_launch
// inputs: x[B,T,I], W_xh[H,I], W_hh[H,H], b_h[H], W_out[O,H], b_out[O]
// output: float [B,T,O]
// ---------------------------------------------------------------------------
extern "C" void kernel_launch(void* const* d_in, const int* in_sizes, int n_in,
                              void* d_out, int out_size) {
    const float* x     = (const float*)d_in[0];
    const float* W_xh  = (const float*)d_in[1];
    const float* W_hh  = (const float*)d_in[2];
    const float* b_h   = (const float*)d_in[3];
    const float* W_out = (const float*)d_in[4];
    const float* b_out = (const float*)d_in[5];
    float* out = (float*)d_out;

    float *xw_p, *h_p, *whhT_p, *wxhT_p, *woutT_p;
    cudaGetSymbolAddress((void**)&xw_p,    g_xw);
    cudaGetSymbolAddress((void**)&h_p,     g_h);
    cudaGetSymbolAddress((void**)&whhT_p,  g_WhhT);
    cudaGetSymbolAddress((void**)&wxhT_p,  g_WxhT);
    cudaGetSymbolAddress((void**)&woutT_p, g_WoutT);

    static bool attr_set = false;
    if (!attr_set) {
        cudaFuncSetAttribute(recurrence3_kernel,
                             cudaFuncAttributeMaxDynamicSharedMemorySize, SMEMB);
        attr_set = true;
    }

    // 1) transposes
    transpose_kernel<<<(H_ * I_ + 255) / 256, 256>>>(W_xh, wxhT_p, H_, I_);
    transpose_kernel<<<(H_ * H_ + 255) / 256, 256>>>(W_hh, whhT_p, H_, H_);
    transpose_kernel<<<(O_ * H_ + 255) / 256, 256>>>(W_out, woutT_p, O_, H_);

    // 2) xw = x @ W_xh^T + b_h -> g_xw  [B*T, H]
    {
        dim3 grid((B_ * T_) / 64, H_ / 64);
        sgemm64<<<grid, 256>>>(x, wxhT_p, b_h, xw_p, B_ * T_, H_, I_);
    }

    // 3) recurrence: g_xw -> g_h  (16 clusters x 8 CTAs)
    recurrence3_kernel<<<16 * CLN, THR, SMEMB>>>();

    // 4) y = h @ W_out^T + b_out -> d_out [B*T, O]
    {
        dim3 grid((B_ * T_) / 64, O_ / 64);
        sgemm64<<<grid, 256>>>(h_p, woutT_p, b_out, out, B_ * T_, O_, H_);
    }
}

// round 13
// speedup vs baseline: 1.3430x; 1.0774x over previous
#include <cuda_runtime.h>
#include <cuda_bf16.h>
#include <math.h>
#include <stdint.h>

// Problem constants
#define B_  256
#define T_  512
#define I_  128
#define H_  512
#define O_  64
#define ALPHA 0.2f
#define BETA_ 8.0f
#define THRESH 20.0f

// Recurrence decomposition: 16 clusters x 8 CTAs; CTA owns 64 cols, cluster owns 16 batches.
#define CLN   8
#define COLS_ 64
#define BB    16
#define THR   256              // 64 cols x 2 batch-octets x 2 k-halves
#define KH    256              // k per half
#define HPAD  20               // floats per h row (80B = 5x16B, aligned)
#define HBUF  (H_ * HPAD)      // 10240 floats per buffer
#define WS_FLOATS (H_ * COLS_) // 32768 floats = 128KB
#define PS_FLOATS (128 * 8)    // reduce scratch: [sid][8]
#define HB_OFF    WS_FLOATS
#define PS_OFF    (WS_FLOATS + 2 * HBUF)
#define SMEM_FLOATS (PS_OFF + PS_FLOATS)
#define SMEMB (SMEM_FLOATS * 4)

// Scratch (device globals; no runtime allocation)
__device__ float g_xw[(size_t)B_ * T_ * H_];
__device__ float g_h [(size_t)B_ * T_ * H_];
__device__ float g_WhhT[H_ * H_];
__device__ float g_WxhT[I_ * H_];
__device__ float g_WoutT[H_ * O_];
__device__ float g_sink;

// ---------------------------------------------------------------------------
__global__ void transpose_kernel(const float* __restrict__ in, float* __restrict__ out,
                                 int R, int C) {
    int idx = blockIdx.x * blockDim.x + threadIdx.x;
    if (idx < R * C) {
        int r = idx / C;
        int c = idx % C;
        out[c * R + r] = in[idx];
    }
}

// Dummy launch (position 5) so ncu -s 5 captures the recurrence; also warms W in L2.
__global__ void prefetch_kernel(const float* __restrict__ w) {
    int idx = blockIdx.x * blockDim.x + threadIdx.x;
    float v = __ldcg(&w[idx & (H_ * H_ - 1)]);
    if (v == 1.2345678e30f) g_sink = v;   // never true; keeps the load alive
}

// ---------------------------------------------------------------------------
// Tiled SGEMM: C[M,N] = A[M,K] * B[K,N] (+ bias[N]); 64x64 tile, BK=32.
// ---------------------------------------------------------------------------
__global__ __launch_bounds__(256) void sgemm64(const float* __restrict__ A,
                                               const float* __restrict__ Bm,
                                               const float* __restrict__ bias,
                                               float* __restrict__ C,
                                               int M, int N, int K) {
    __shared__ float As[32][65];
    __shared__ float Bs[32][64];

    int tid = threadIdx.x;
    int m0 = blockIdx.x * 64;
    int n0 = blockIdx.y * 64;
    int tx = tid % 16;
    int ty = tid / 16;

    int a_k = tid % 32;
    int a_m = tid / 32;
    int b_n = tid % 64;
    int b_k = tid / 64;

    float acc[4][4];
#pragma unroll
    for (int i = 0; i < 4; i++)
#pragma unroll
        for (int j = 0; j < 4; j++) acc[i][j] = 0.0f;

    for (int k0 = 0; k0 < K; k0 += 32) {
#pragma unroll
        for (int i = 0; i < 8; i++)
            As[a_k][a_m + 8 * i] = A[(size_t)(m0 + a_m + 8 * i) * K + (k0 + a_k)];
#pragma unroll
        for (int i = 0; i < 8; i++)
            Bs[b_k + 4 * i][b_n] = Bm[(size_t)(k0 + b_k + 4 * i) * N + (n0 + b_n)];
        __syncthreads();

#pragma unroll
        for (int kk = 0; kk < 32; kk++) {
            float a[4], b[4];
#pragma unroll
            for (int i = 0; i < 4; i++) a[i] = As[kk][ty * 4 + i];
#pragma unroll
            for (int j = 0; j < 4; j++) b[j] = Bs[kk][tx * 4 + j];
#pragma unroll
            for (int i = 0; i < 4; i++)
#pragma unroll
                for (int j = 0; j < 4; j++) acc[i][j] += a[i] * b[j];
        }
        __syncthreads();
    }

#pragma unroll
    for (int i = 0; i < 4; i++) {
        size_t row = (size_t)(m0 + ty * 4 + i);
#pragma unroll
        for (int j = 0; j < 4; j++) {
            int col = n0 + tx * 4 + j;
            float v = acc[i][j];
            if (bias) v += bias[col];
            C[row * N + col] = v;
        }
    }
}

// ---------------------------------------------------------------------------
__device__ __forceinline__ float phi_fn(float x) {
    float z = BETA_ * x;
    if (z > THRESH) return x;
    return log1pf(expf(z)) * (1.0f / BETA_);
}

__device__ __forceinline__ uint32_t smem_u32(const void* p) {
    uint32_t a;
    asm("{ .reg .u64 t; cvta.to.shared.u64 t, %1; cvt.u32.u64 %0, t; }" : "=r"(a) : "l"(p));
    return a;
}

__device__ __forceinline__ unsigned long long pack2(float lo, float hi) {
    unsigned long long r;
    asm("mov.b64 %0, {%1, %2};" : "=l"(r) : "r"(__float_as_uint(lo)), "r"(__float_as_uint(hi)));
    return r;
}

__device__ __forceinline__ void unpack2(unsigned long long v, float& lo, float& hi) {
    uint32_t a, b;
    asm("mov.b64 {%0, %1}, %2;" : "=r"(a), "=r"(b) : "l"(v));
    lo = __uint_as_float(a);
    hi = __uint_as_float(b);
}

__device__ __forceinline__ void fma2(unsigned long long& acc, unsigned long long h,
                                     unsigned long long w) {
    asm("fma.rn.f32x2 %0, %1, %2, %0;" : "+l"(acc) : "l"(h), "l"(w));
}

__device__ __forceinline__ uint32_t mapa_rank(uint32_t laddr, int rank) {
    uint32_t ra;
    asm("mapa.shared::cluster.u32 %0, %1, %2;" : "=r"(ra) : "r"(laddr), "r"(rank));
    return ra;
}

__device__ __forceinline__ void st_cluster_v4_u(uint32_t addr,
                                                float a, float b, float c, float d) {
    asm volatile("st.shared::cluster.v4.f32 [%0], {%1, %2, %3, %4};"
                 :: "r"(addr), "f"(a), "f"(b), "f"(c), "f"(d) : "memory");
}

// ---------------------------------------------------------------------------
// Recurrence v5: clusters of 8 CTAs; 256 thr = 64 cols x 2 batch-octets x 2 k-halves.
// Proven per-step cluster barrier (R6) + k-split for 2 warps/SMSP + early xw loads.
// ---------------------------------------------------------------------------
__global__ __launch_bounds__(THR, 1) __cluster_dims__(CLN, 1, 1)
void recurrence5_kernel() {
    extern __shared__ float smem[];
    float* Ws = smem;                 // [k][jl] stride 64
    float* hb = smem + HB_OFF;        // [p][k][b] stride HPAD
    float* ps = smem + PS_OFF;        // [sid][8]

    const int tid = threadIdx.x;
    uint32_t rank;
    asm("mov.u32 %0, %%cluster_ctarank;" : "=r"(rank));
    const int bg  = blockIdx.x / CLN;
    const int jl  = tid & 63;
    const int bq  = (tid >> 6) & 1;
    const int kh  = tid >> 7;
    const int sid = tid & 127;
    const int jg  = (int)rank * COLS_ + jl;
    const int bbase = bg * BB + bq * 8;

    const uint32_t smem_base = smem_u32(smem);

    // ---- init: W slice into SMEM, zero h buffers ----
    {
        const float* __restrict__ WhhT = g_WhhT;
        const int j0 = (int)rank * COLS_;
        for (int idx = tid; idx < WS_FLOATS; idx += THR) {
            int k = idx >> 6;
            int c = idx & 63;
            Ws[idx] = WhhT[k * H_ + j0 + c];
        }
    }
    for (int idx = tid; idx < 2 * HBUF; idx += THR) hb[idx] = 0.0f;
    __syncthreads();
    asm volatile("barrier.cluster.arrive.aligned;" ::: "memory");
    asm volatile("barrier.cluster.wait.aligned;" ::: "memory");

    // precompute remote smem bases for this thread's 4 send targets
    uint32_t rbase[4];
#pragma unroll
    for (int c = 0; c < 4; c++) rbase[c] = mapa_rank(smem_base, kh * 4 + c);

    const float* __restrict__ xwb = g_xw + (size_t)bbase * T_ * H_ + jg;
    float*       __restrict__ hob = g_h  + (size_t)bbase * T_ * H_ + jg;

    float hold[8];
#pragma unroll
    for (int i = 0; i < 8; i++) hold[i] = 0.0f;

    const int kbase = kh * KH;

    for (int t = 0; t < T_; t++) {
        const int p  = t & 1;
        const int p2 = p ^ 1;

        // xw loads issued early (kh==0 only), consumed after the ~4K-cycle k-loop
        float xv[8];
        if (kh == 0) {
#pragma unroll
            for (int i = 0; i < 8; i++)
                xv[i] = __ldcs(xwb + ((size_t)i * T_ + t) * H_);
        }

        // ---- partial matvec over this thread's k-half ----
        unsigned long long a0 = 0, a1 = 0, a2 = 0, a3 = 0;
        const float* __restrict__ wp = Ws + jl;
        const float* __restrict__ hp = hb + p * HBUF + bq * 8;
#pragma unroll 8
        for (int kk = 0; kk < KH; kk++) {
            const int k = kbase + kk;
            float w = wp[(size_t)k * COLS_];
            unsigned long long w2;
            asm("mov.b64 %0, {%1, %1};" : "=l"(w2) : "r"(__float_as_uint(w)));
            const ulonglong2* hv = reinterpret_cast<const ulonglong2*>(hp + (size_t)k * HPAD);
            ulonglong2 hA = hv[0];   // batches 0..3 of this octet (broadcast read)
            ulonglong2 hB = hv[1];   // batches 4..7
            fma2(a0, hA.x, w2);
            fma2(a1, hA.y, w2);
            fma2(a2, hB.x, w2);
            fma2(a3, hB.y, w2);
        }

        if (kh == 1) {   // publish partials
            ulonglong2* pp = reinterpret_cast<ulonglong2*>(ps + (size_t)sid * 8);
            pp[0] = make_ulonglong2(a0, a1);
            pp[1] = make_ulonglong2(a2, a3);
        }
        __syncthreads();

        unsigned long long v01, v23, v45, v67;
        if (kh == 0) {   // reduce + activation + global stash + publish final h
            const ulonglong2* pp = reinterpret_cast<const ulonglong2*>(ps + (size_t)sid * 8);
            ulonglong2 q0 = pp[0];
            ulonglong2 q1 = pp[1];
            float s[8], r[8];
            unpack2(a0, s[0], s[1]); unpack2(a1, s[2], s[3]);
            unpack2(a2, s[4], s[5]); unpack2(a3, s[6], s[7]);
            unpack2(q0.x, r[0], r[1]); unpack2(q0.y, r[2], r[3]);
            unpack2(q1.x, r[4], r[5]); unpack2(q1.y, r[6], r[7]);
            float hn[8];
#pragma unroll
            for (int i = 0; i < 8; i++) {
                float pre = s[i] + r[i] + xv[i];
                hn[i] = (1.0f - ALPHA) * hold[i] + ALPHA * phi_fn(pre);
                hold[i] = hn[i];
            }
#pragma unroll
            for (int i = 0; i < 8; i++)
                hob[((size_t)i * T_ + t) * H_] = hn[i];
            v01 = pack2(hn[0], hn[1]); v23 = pack2(hn[2], hn[3]);
            v45 = pack2(hn[4], hn[5]); v67 = pack2(hn[6], hn[7]);
            ulonglong2* pw = reinterpret_cast<ulonglong2*>(ps + (size_t)sid * 8);
            pw[0] = make_ulonglong2(v01, v23);
            pw[1] = make_ulonglong2(v45, v67);
        }
        __syncthreads();

        if (t < T_ - 1) {
            if (kh == 1) {   // fetch final h for this (jl,bq)
                const ulonglong2* pr = reinterpret_cast<const ulonglong2*>(ps + (size_t)sid * 8);
                ulonglong2 u0 = pr[0];
                ulonglong2 u1 = pr[1];
                v01 = u0.x; v23 = u0.y; v45 = u1.x; v67 = u1.y;
            }
            float h0, h1, h2, h3, h4, h5, h6, h7;
            unpack2(v01, h0, h1); unpack2(v23, h2, h3);
            unpack2(v45, h4, h5); unpack2(v67, h6, h7);

            // send h_t[jg][8 batches] to this half's 4 ranks
            const uint32_t doff = (uint32_t)(HB_OFF + p2 * HBUF + jg * HPAD + bq * 8) * 4u;
#pragma unroll
            for (int c = 0; c < 4; c++) {
                const uint32_t da = rbase[c] + doff;
                st_cluster_v4_u(da,       h0, h1, h2, h3);
                st_cluster_v4_u(da + 16u, h4, h5, h6, h7);
            }

            // cluster barrier: all exchange writes visible; reads of buffer p done
            asm volatile("barrier.cluster.arrive.aligned;" ::: "memory");
            asm volatile("barrier.cluster.wait.aligned;" ::: "memory");
        }
    }
}

// ---------------------------------------------------------------------------
// kernel_launch
// inputs: x[B,T,I], W_xh[H,I], W_hh[H,H], b_h[H], W_out[O,H], b_out[O]
// output: float [B,T,O]
// ---------------------------------------------------------------------------
extern "C" void kernel_launch(void* const* d_in, const int* in_sizes, int n_in,
                              void* d_out, int out_size) {
    const float* x     = (const float*)d_in[0];
    const float* W_xh  = (const float*)d_in[1];
    const float* W_hh  = (const float*)d_in[2];
    const float* b_h   = (const float*)d_in[3];
    const float* W_out = (const float*)d_in[4];
    const float* b_out = (const float*)d_in[5];
    float* out = (float*)d_out;

    float *xw_p, *h_p, *whhT_p, *wxhT_p, *woutT_p;
    cudaGetSymbolAddress((void**)&xw_p,    g_xw);
    cudaGetSymbolAddress((void**)&h_p,     g_h);
    cudaGetSymbolAddress((void**)&whhT_p,  g_WhhT);
    cudaGetSymbolAddress((void**)&wxhT_p,  g_WxhT);
    cudaGetSymbolAddress((void**)&woutT_p, g_WoutT);

    static bool attr_set = false;
    if (!attr_set) {
        cudaFuncSetAttribute(recurrence5_kernel,
                             cudaFuncAttributeMaxDynamicSharedMemorySize, SMEMB);
        attr_set = true;
    }

    // launches 1-3: transposes
    transpose_kernel<<<(H_ * I_ + 255) / 256, 256>>>(W_xh, wxhT_p, H_, I_);
    transpose_kernel<<<(H_ * H_ + 255) / 256, 256>>>(W_hh, whhT_p, H_, H_);
    transpose_kernel<<<(O_ * H_ + 255) / 256, 256>>>(W_out, woutT_p, O_, H_);

    // launch 4: xw = x @ W_xh^T + b_h -> g_xw
    {
        dim3 grid((B_ * T_) / 64, H_ / 64);
        sgemm64<<<grid, 256>>>(x, wxhT_p, b_h, xw_p, B_ * T_, H_, I_);
    }

    // launch 5: dummy/prefetch (positions recurrence as launch 6 for ncu -s 5 -c 1)
    prefetch_kernel<<<H_ * H_ / 256, 256>>>(whhT_p);

    // launch 6: recurrence
    recurrence5_kernel<<<16 * CLN, THR, SMEMB>>>();

    // launch 7: y = h @ W_out^T + b_out
    {
        dim3 grid((B_ * T_) / 64, O_ / 64);
        sgemm64<<<grid, 256>>>(h_p, woutT_p, b_out, out, B_ * T_, O_, H_);
    }
}

// round 14
// speedup vs baseline: 1.4024x; 1.0442x over previous
#include <cuda_runtime.h>
#include <cuda_bf16.h>
#include <math.h>
#include <stdint.h>

// Problem constants
#define B_  256
#define T_  512
#define I_  128
#define H_  512
#define O_  64
#define ALPHA 0.2f
#define BETA_ 8.0f
#define THRESH 20.0f

// Recurrence decomposition: 16 clusters x 8 CTAs; CTA owns 64 cols, cluster owns 16 batches.
#define CLN   8
#define COLS_ 64
#define BB    16
#define THR   256              // 64 cols x 4 batch-quads, full k per thread
#define HPAD  20               // floats per h row (80B, 16B-aligned quads)
#define HBUF  (H_ * HPAD)      // 10240 floats per buffer
#define WS_FLOATS (H_ * COLS_) // 32768 floats = 128KB
#define HB_OFF    WS_FLOATS
#define SMEM_FLOATS (WS_FLOATS + 2 * HBUF)
#define SMEMB (SMEM_FLOATS * 4)   // 212992 bytes

// Scratch (device globals; no runtime allocation)
__device__ float g_xw[(size_t)B_ * T_ * H_];
__device__ float g_h [(size_t)B_ * T_ * H_];
__device__ float g_WhhT[H_ * H_];
__device__ float g_WxhT[I_ * H_];
__device__ float g_WoutT[H_ * O_];
__device__ float g_sink;

// ---------------------------------------------------------------------------
__global__ void transpose_kernel(const float* __restrict__ in, float* __restrict__ out,
                                 int R, int C) {
    int idx = blockIdx.x * blockDim.x + threadIdx.x;
    if (idx < R * C) {
        int r = idx / C;
        int c = idx % C;
        out[c * R + r] = in[idx];
    }
}

// Dummy launch; also warms W in L2.
__global__ void prefetch_kernel(const float* __restrict__ w) {
    int idx = blockIdx.x * blockDim.x + threadIdx.x;
    float v = __ldcg(&w[idx & (H_ * H_ - 1)]);
    if (v == 1.2345678e30f) g_sink = v;   // never true; keeps the load alive
}

// ---------------------------------------------------------------------------
// Tiled SGEMM: C[M,N] = A[M,K] * B[K,N] (+ bias[N]); 64x64 tile, BK=32.
// ---------------------------------------------------------------------------
__global__ __launch_bounds__(256) void sgemm64(const float* __restrict__ A,
                                               const float* __restrict__ Bm,
                                               const float* __restrict__ bias,
                                               float* __restrict__ C,
                                               int M, int N, int K) {
    __shared__ float As[32][65];
    __shared__ float Bs[32][64];

    int tid = threadIdx.x;
    int m0 = blockIdx.x * 64;
    int n0 = blockIdx.y * 64;
    int tx = tid % 16;
    int ty = tid / 16;

    int a_k = tid % 32;
    int a_m = tid / 32;
    int b_n = tid % 64;
    int b_k = tid / 64;

    float acc[4][4];
#pragma unroll
    for (int i = 0; i < 4; i++)
#pragma unroll
        for (int j = 0; j < 4; j++) acc[i][j] = 0.0f;

    for (int k0 = 0; k0 < K; k0 += 32) {
#pragma unroll
        for (int i = 0; i < 8; i++)
            As[a_k][a_m + 8 * i] = A[(size_t)(m0 + a_m + 8 * i) * K + (k0 + a_k)];
#pragma unroll
        for (int i = 0; i < 8; i++)
            Bs[b_k + 4 * i][b_n] = Bm[(size_t)(k0 + b_k + 4 * i) * N + (n0 + b_n)];
        __syncthreads();

#pragma unroll
        for (int kk = 0; kk < 32; kk++) {
            float a[4], b[4];
#pragma unroll
            for (int i = 0; i < 4; i++) a[i] = As[kk][ty * 4 + i];
#pragma unroll
            for (int j = 0; j < 4; j++) b[j] = Bs[kk][tx * 4 + j];
#pragma unroll
            for (int i = 0; i < 4; i++)
#pragma unroll
                for (int j = 0; j < 4; j++) acc[i][j] += a[i] * b[j];
        }
        __syncthreads();
    }

#pragma unroll
    for (int i = 0; i < 4; i++) {
        size_t row = (size_t)(m0 + ty * 4 + i);
#pragma unroll
        for (int j = 0; j < 4; j++) {
            int col = n0 + tx * 4 + j;
            float v = acc[i][j];
            if (bias) v += bias[col];
            C[row * N + col] = v;
        }
    }
}

// ---------------------------------------------------------------------------
// fast phi: softplus(x, beta=8, threshold=20) with MUFU-based exp/log.
// abs err ~1e-7 on h — negligible vs 1e-3 tolerance.
__device__ __forceinline__ float phi_fn(float x) {
    float z = BETA_ * x;
    if (z > THRESH) return x;
    return __logf(1.0f + __expf(z)) * 0.125f;
}

__device__ __forceinline__ uint32_t smem_u32(const void* p) {
    uint32_t a;
    asm("{ .reg .u64 t; cvta.to.shared.u64 t, %1; cvt.u32.u64 %0, t; }" : "=r"(a) : "l"(p));
    return a;
}

__device__ __forceinline__ unsigned long long pack2(float lo, float hi) {
    unsigned long long r;
    asm("mov.b64 %0, {%1, %2};" : "=l"(r) : "r"(__float_as_uint(lo)), "r"(__float_as_uint(hi)));
    return r;
}

__device__ __forceinline__ void unpack2(unsigned long long v, float& lo, float& hi) {
    uint32_t a, b;
    asm("mov.b64 {%0, %1}, %2;" : "=r"(a), "=r"(b) : "l"(v));
    lo = __uint_as_float(a);
    hi = __uint_as_float(b);
}

__device__ __forceinline__ void fma2(unsigned long long& acc, unsigned long long h,
                                     unsigned long long w) {
    asm("fma.rn.f32x2 %0, %1, %2, %0;" : "+l"(acc) : "l"(h), "l"(w));
}

__device__ __forceinline__ uint32_t mapa_rank(uint32_t laddr, int rank) {
    uint32_t ra;
    asm("mapa.shared::cluster.u32 %0, %1, %2;" : "=r"(ra) : "r"(laddr), "r"(rank));
    return ra;
}

__device__ __forceinline__ void st_cluster_v4_u(uint32_t addr,
                                                float a, float b, float c, float d) {
    asm volatile("st.shared::cluster.v4.f32 [%0], {%1, %2, %3, %4};"
                 :: "r"(addr), "f"(a), "f"(b), "f"(c), "f"(d) : "memory");
}

// ---------------------------------------------------------------------------
// Recurrence v6: clusters of 8 CTAs; 256 thr = 64 cols x 4 batch-quads, FULL k
// per thread. No intra-CTA communication in the loop (no syncthreads, no reduce).
// One split arrive/wait cluster barrier per step; STG + next-step xw loads hide
// under the barrier wait.
// ---------------------------------------------------------------------------
__global__ __launch_bounds__(THR, 1) __cluster_dims__(CLN, 1, 1)
void recurrence6_kernel() {
    extern __shared__ float smem[];
    float* Ws = smem;                 // [k][jl] stride 64
    float* hb = smem + HB_OFF;        // [p][k][b] stride HPAD

    const int tid = threadIdx.x;
    uint32_t rank;
    asm("mov.u32 %0, %%cluster_ctarank;" : "=r"(rank));
    const int bg = blockIdx.x / CLN;
    const int jl = tid & 63;          // column within CTA
    const int q  = tid >> 6;          // batch quad 0..3
    const int jg = (int)rank * COLS_ + jl;
    const int bbase = bg * BB + q * 4;

    const uint32_t smem_base = smem_u32(smem);

    // ---- init: W slice into SMEM, zero both h buffers ----
    {
        const float* __restrict__ WhhT = g_WhhT;
        const int j0 = (int)rank * COLS_;
        for (int idx = tid; idx < WS_FLOATS; idx += THR) {
            int k = idx >> 6;
            int c = idx & 63;
            Ws[idx] = WhhT[k * H_ + j0 + c];
        }
    }
    for (int idx = tid; idx < 2 * HBUF; idx += THR) hb[idx] = 0.0f;
    __syncthreads();
    asm volatile("barrier.cluster.arrive.aligned;" ::: "memory");
    asm volatile("barrier.cluster.wait.aligned;" ::: "memory");

    // remote smem bases for all 8 ranks
    uint32_t rbase[8];
#pragma unroll
    for (int c = 0; c < CLN; c++) rbase[c] = mapa_rank(smem_base, c);

    const float* __restrict__ xwb = g_xw + (size_t)bbase * T_ * H_ + jg;
    float*       __restrict__ hob = g_h  + (size_t)bbase * T_ * H_ + jg;

    float hold[4];
#pragma unroll
    for (int i = 0; i < 4; i++) hold[i] = 0.0f;

    // xw for t=0
    float xv[4];
#pragma unroll
    for (int i = 0; i < 4; i++)
        xv[i] = __ldcs(xwb + (size_t)i * T_ * H_);

    for (int t = 0; t < T_; t++) {
        const int p  = t & 1;
        const int p2 = p ^ 1;

        // ---- full-k matvec for (jl, 4 batches); xw folded into acc init ----
        unsigned long long a0 = pack2(xv[0], xv[1]);
        unsigned long long a1 = pack2(xv[2], xv[3]);
        const float* __restrict__ wp = Ws + jl;
        const float* __restrict__ hp = hb + p * HBUF + q * 4;
#pragma unroll 8
        for (int k = 0; k < H_; k++) {
            float w = wp[k * COLS_];                // coalesced 128B/warp
            unsigned long long w2;
            asm("mov.b64 %0, {%1, %1};" : "=l"(w2) : "r"(__float_as_uint(w)));
            ulonglong2 hq = *reinterpret_cast<const ulonglong2*>(hp + k * HPAD); // broadcast
            fma2(a0, hq.x, w2);
            fma2(a1, hq.y, w2);
        }

        // ---- activation + leak (fully thread-local) ----
        float s[4];
        unpack2(a0, s[0], s[1]);
        unpack2(a1, s[2], s[3]);
        float hn[4];
#pragma unroll
        for (int i = 0; i < 4; i++) {
            hn[i] = (1.0f - ALPHA) * hold[i] + ALPHA * phi_fn(s[i]);
            hold[i] = hn[i];
        }

        if (t < T_ - 1) {
            // ---- send h_t[jg][quad] into every CTA's next buffer ----
            const uint32_t doff = (uint32_t)(HB_OFF + p2 * HBUF + jg * HPAD + q * 4) * 4u;
#pragma unroll
            for (int c = 0; c < CLN; c++)
                st_cluster_v4_u(rbase[c] + doff, hn[0], hn[1], hn[2], hn[3]);

            asm volatile("barrier.cluster.arrive.aligned;" ::: "memory");

            // ---- hidden under barrier: global stash + next-step xw loads ----
#pragma unroll
            for (int i = 0; i < 4; i++)
                hob[((size_t)i * T_ + t) * H_] = hn[i];
#pragma unroll
            for (int i = 0; i < 4; i++)
                xv[i] = __ldcs(xwb + ((size_t)i * T_ + (t + 1)) * H_);

            asm volatile("barrier.cluster.wait.aligned;" ::: "memory");
        } else {
#pragma unroll
            for (int i = 0; i < 4; i++)
                hob[((size_t)i * T_ + t) * H_] = hn[i];
        }
    }
}

// ---------------------------------------------------------------------------
// kernel_launch
// inputs: x[B,T,I], W_xh[H,I], W_hh[H,H], b_h[H], W_out[O,H], b_out[O]
// output: float [B,T,O]
// ---------------------------------------------------------------------------
extern "C" void kernel_launch(void* const* d_in, const int* in_sizes, int n_in,
                              void* d_out, int out_size) {
    const float* x     = (const float*)d_in[0];
    const float* W_xh  = (const float*)d_in[1];
    const float* W_hh  = (const float*)d_in[2];
    const float* b_h   = (const float*)d_in[3];
    const float* W_out = (const float*)d_in[4];
    const float* b_out = (const float*)d_in[5];
    float* out = (float*)d_out;

    float *xw_p, *h_p, *whhT_p, *wxhT_p, *woutT_p;
    cudaGetSymbolAddress((void**)&xw_p,    g_xw);
    cudaGetSymbolAddress((void**)&h_p,     g_h);
    cudaGetSymbolAddress((void**)&whhT_p,  g_WhhT);
    cudaGetSymbolAddress((void**)&wxhT_p,  g_WxhT);
    cudaGetSymbolAddress((void**)&woutT_p, g_WoutT);

    static bool attr_set = false;
    if (!attr_set) {
        cudaFuncSetAttribute(recurrence6_kernel,
                             cudaFuncAttributeMaxDynamicSharedMemorySize, SMEMB);
        attr_set = true;
    }

    // transposes
    transpose_kernel<<<(H_ * I_ + 255) / 256, 256>>>(W_xh, wxhT_p, H_, I_);
    transpose_kernel<<<(H_ * H_ + 255) / 256, 256>>>(W_hh, whhT_p, H_, H_);
    transpose_kernel<<<(O_ * H_ + 255) / 256, 256>>>(W_out, woutT_p, O_, H_);

    // xw = x @ W_xh^T + b_h -> g_xw
    {
        dim3 grid((B_ * T_) / 64, H_ / 64);
        sgemm64<<<grid, 256>>>(x, wxhT_p, b_h, xw_p, B_ * T_, H_, I_);
    }

    // dummy/prefetch (keeps recurrence at a fixed launch index for ncu)
    prefetch_kernel<<<H_ * H_ / 256, 256>>>(whhT_p);

    // recurrence: g_xw -> g_h
    recurrence6_kernel<<<16 * CLN, THR, SMEMB>>>();

    // y = h @ W_out^T + b_out
    {
        dim3 grid((B_ * T_) / 64, O_ / 64);
        sgemm64<<<grid, 256>>>(h_p, woutT_p, b_out, out, B_ * T_, O_, H_);
    }
}

// round 15
// speedup vs baseline: 1.4124x; 1.0071x over previous
#include <cuda_runtime.h>
#include <cuda_bf16.h>
#include <math.h>
#include <stdint.h>

// Problem constants
#define B_  256
#define T_  512
#define I_  128
#define H_  512
#define O_  64
#define ALPHA 0.2f
#define BETA_ 8.0f
#define THRESH 20.0f

// Recurrence decomposition: 16 clusters x 8 CTAs; CTA owns 64 cols, cluster owns 16 batches.
#define CLN   8
#define COLS_ 64
#define BB    16
#define NBG   16
#define THR   256              // 64 cols x 4 batch-quads, full k per thread
#define HPAD  20               // floats per h row (80B, 16B-aligned quads)
#define HBUF  (H_ * HPAD)      // 10240 floats (single buffer now)
#define WS_FLOATS (H_ * COLS_) // 32768 floats = 128KB
#define HB_OFF    WS_FLOATS
#define SMEM_FLOATS (WS_FLOATS + HBUF)
#define SMEMB (SMEM_FLOATS * 4)   // 172032 bytes

// Scratch (device globals; no runtime allocation)
__device__ float g_xw[(size_t)B_ * T_ * H_];
__device__ float g_h [(size_t)B_ * T_ * H_];
__device__ float g_WhhT[H_ * H_];
__device__ float g_WxhT[I_ * H_];
__device__ float g_WoutT[H_ * O_];
// L2 exchange slots: [parity][bg][k][b16]  (1 MB total, L2-resident)
__device__ float g_hx[2][NBG][H_][BB];

// ---------------------------------------------------------------------------
__global__ void transpose_kernel(const float* __restrict__ in, float* __restrict__ out,
                                 int R, int C) {
    int idx = blockIdx.x * blockDim.x + threadIdx.x;
    if (idx < R * C) {
        int r = idx / C;
        int c = idx % C;
        out[c * R + r] = in[idx];
    }
}

// ---------------------------------------------------------------------------
// Tiled SGEMM: C[M,N] = A[M,K] * B[K,N] (+ bias[N]); 64x64 tile, BK=32.
// ---------------------------------------------------------------------------
__global__ __launch_bounds__(256) void sgemm64(const float* __restrict__ A,
                                               const float* __restrict__ Bm,
                                               const float* __restrict__ bias,
                                               float* __restrict__ C,
                                               int M, int N, int K) {
    __shared__ float As[32][65];
    __shared__ float Bs[32][64];

    int tid = threadIdx.x;
    int m0 = blockIdx.x * 64;
    int n0 = blockIdx.y * 64;
    int tx = tid % 16;
    int ty = tid / 16;

    int a_k = tid % 32;
    int a_m = tid / 32;
    int b_n = tid % 64;
    int b_k = tid / 64;

    float acc[4][4];
#pragma unroll
    for (int i = 0; i < 4; i++)
#pragma unroll
        for (int j = 0; j < 4; j++) acc[i][j] = 0.0f;

    for (int k0 = 0; k0 < K; k0 += 32) {
#pragma unroll
        for (int i = 0; i < 8; i++)
            As[a_k][a_m + 8 * i] = A[(size_t)(m0 + a_m + 8 * i) * K + (k0 + a_k)];
#pragma unroll
        for (int i = 0; i < 8; i++)
            Bs[b_k + 4 * i][b_n] = Bm[(size_t)(k0 + b_k + 4 * i) * N + (n0 + b_n)];
        __syncthreads();

#pragma unroll
        for (int kk = 0; kk < 32; kk++) {
            float a[4], b[4];
#pragma unroll
            for (int i = 0; i < 4; i++) a[i] = As[kk][ty * 4 + i];
#pragma unroll
            for (int j = 0; j < 4; j++) b[j] = Bs[kk][tx * 4 + j];
#pragma unroll
            for (int i = 0; i < 4; i++)
#pragma unroll
                for (int j = 0; j < 4; j++) acc[i][j] += a[i] * b[j];
        }
        __syncthreads();
    }

#pragma unroll
    for (int i = 0; i < 4; i++) {
        size_t row = (size_t)(m0 + ty * 4 + i);
#pragma unroll
        for (int j = 0; j < 4; j++) {
            int col = n0 + tx * 4 + j;
            float v = acc[i][j];
            if (bias) v += bias[col];
            C[row * N + col] = v;
        }
    }
}

// ---------------------------------------------------------------------------
// fast phi: softplus(x, beta=8, threshold=20) with MUFU-based exp/log.
__device__ __forceinline__ float phi_fn(float x) {
    float z = BETA_ * x;
    if (z > THRESH) return x;
    return __logf(1.0f + __expf(z)) * 0.125f;
}

__device__ __forceinline__ unsigned long long pack2(float lo, float hi) {
    unsigned long long r;
    asm("mov.b64 %0, {%1, %2};" : "=l"(r) : "r"(__float_as_uint(lo)), "r"(__float_as_uint(hi)));
    return r;
}

__device__ __forceinline__ void unpack2(unsigned long long v, float& lo, float& hi) {
    uint32_t a, b;
    asm("mov.b64 {%0, %1}, %2;" : "=r"(a), "=r"(b) : "l"(v));
    lo = __uint_as_float(a);
    hi = __uint_as_float(b);
}

__device__ __forceinline__ void fma2(unsigned long long& acc, unsigned long long h,
                                     unsigned long long w) {
    asm("fma.rn.f32x2 %0, %1, %2, %0;" : "+l"(acc) : "l"(h), "l"(w));
}

// ---------------------------------------------------------------------------
// Recurrence v7: clusters of 8 CTAs used ONLY for the HW barrier.
// h exchange routed through L2 (__stcg publish -> arrive(release)/wait(acquire)
// -> __ldcg restage into SMEM). No DSMEM data traffic at all.
// 256 thr = 64 cols x 4 batch-quads, full k per thread, no intra-CTA reduce.
// ---------------------------------------------------------------------------
__global__ __launch_bounds__(THR, 1) __cluster_dims__(CLN, 1, 1)
void recurrence7_kernel() {
    extern __shared__ float smem[];
    float* Ws = smem;                 // [k][jl] stride 64
    float* hs = smem + HB_OFF;        // [k][b] stride HPAD (single buffer)

    const int tid = threadIdx.x;
    uint32_t rank;
    asm("mov.u32 %0, %%cluster_ctarank;" : "=r"(rank));
    const int bg = blockIdx.x / CLN;
    const int jl = tid & 63;          // column within CTA
    const int q  = tid >> 6;          // batch quad 0..3
    const int jg = (int)rank * COLS_ + jl;
    const int bbase = bg * BB + q * 4;

    // ---- init: W slice into SMEM, zero h buffer ----
    {
        const float* __restrict__ WhhT = g_WhhT;
        const int j0 = (int)rank * COLS_;
        for (int idx = tid; idx < WS_FLOATS; idx += THR) {
            int k = idx >> 6;
            int c = idx & 63;
            Ws[idx] = WhhT[k * H_ + j0 + c];
        }
    }
    for (int idx = tid; idx < HBUF; idx += THR) hs[idx] = 0.0f;
    __syncthreads();
    asm volatile("barrier.cluster.arrive.aligned;" ::: "memory");
    asm volatile("barrier.cluster.wait.aligned;" ::: "memory");

    const float* __restrict__ xwb = g_xw + (size_t)bbase * T_ * H_ + jg;
    float*       __restrict__ hob = g_h  + (size_t)bbase * T_ * H_ + jg;

    // stage assignment: warp w restages k-rows [w*64, w*64+64) of the slot.
    const int warp = tid >> 5;
    const int lane = tid & 31;
    const int stage_base = warp * 256;     // float4 index into [512][16] slot

    float hold[4];
#pragma unroll
    for (int i = 0; i < 4; i++) hold[i] = 0.0f;

    // xw for t=0
    float xv[4];
#pragma unroll
    for (int i = 0; i < 4; i++)
        xv[i] = __ldcs(xwb + (size_t)i * T_ * H_);

    for (int t = 0; t < T_; t++) {
        const int sl = t & 1;   // slot receiving h_t

        // ---- full-k matvec for (jl, 4 batches); xw folded into acc init ----
        unsigned long long a0 = pack2(xv[0], xv[1]);
        unsigned long long a1 = pack2(xv[2], xv[3]);
        const float* __restrict__ wp = Ws + jl;
        const float* __restrict__ hp = hs + q * 4;
#pragma unroll 8
        for (int k = 0; k < H_; k++) {
            float w = wp[k * COLS_];                 // coalesced 128B/warp
            unsigned long long w2;
            asm("mov.b64 %0, {%1, %1};" : "=l"(w2) : "r"(__float_as_uint(w)));
            ulonglong2 hq = *reinterpret_cast<const ulonglong2*>(hp + k * HPAD); // broadcast
            fma2(a0, hq.x, w2);
            fma2(a1, hq.y, w2);
        }

        // ---- activation + leak (thread-local) ----
        float s[4];
        unpack2(a0, s[0], s[1]);
        unpack2(a1, s[2], s[3]);
        float hn[4];
#pragma unroll
        for (int i = 0; i < 4; i++) {
            hn[i] = (1.0f - ALPHA) * hold[i] + ALPHA * phi_fn(s[i]);
            hold[i] = hn[i];
        }

        // ---- publish h_t to L2 slot (one STG.128) ----
        __stcg(reinterpret_cast<float4*>(&g_hx[sl][bg][jg][q * 4]),
               make_float4(hn[0], hn[1], hn[2], hn[3]));

        if (t < T_ - 1) {
            asm volatile("barrier.cluster.arrive.aligned;" ::: "memory");

            // hidden under the barrier: global h stash + next-step xw loads
#pragma unroll
            for (int i = 0; i < 4; i++)
                __stcs(hob + ((size_t)i * T_ + t) * H_, hn[i]);
#pragma unroll
            for (int i = 0; i < 4; i++)
                xv[i] = __ldcs(xwb + ((size_t)i * T_ + (t + 1)) * H_);

            asm volatile("barrier.cluster.wait.aligned;" ::: "memory");

            // ---- restage full h_t slot (32KB) from L2 into SMEM ----
            const float4* __restrict__ src =
                reinterpret_cast<const float4*>(&g_hx[sl][bg][0][0]);
            float4 v[8];
#pragma unroll
            for (int j = 0; j < 8; j++)
                v[j] = __ldcg(src + stage_base + j * 32 + lane);   // coalesced
#pragma unroll
            for (int j = 0; j < 8; j++) {
                int idx = stage_base + j * 32 + lane;
                int k   = idx >> 2;
                int bq  = idx & 3;
                *reinterpret_cast<float4*>(&hs[k * HPAD + bq * 4]) = v[j];
            }
            __syncthreads();
        } else {
#pragma unroll
            for (int i = 0; i < 4; i++)
                __stcs(hob + ((size_t)i * T_ + t) * H_, hn[i]);
        }
    }
}

// ---------------------------------------------------------------------------
// kernel_launch
// inputs: x[B,T,I], W_xh[H,I], W_hh[H,H], b_h[H], W_out[O,H], b_out[O]
// output: float [B,T,O]
// Launch order puts the recurrence at index 3 (2 harness-internal launches
// precede ours -> ncu -s 5 should finally capture the recurrence).
// ---------------------------------------------------------------------------
extern "C" void kernel_launch(void* const* d_in, const int* in_sizes, int n_in,
                              void* d_out, int out_size) {
    const float* x     = (const float*)d_in[0];
    const float* W_xh  = (const float*)d_in[1];
    const float* W_hh  = (const float*)d_in[2];
    const float* b_h   = (const float*)d_in[3];
    const float* W_out = (const float*)d_in[4];
    const float* b_out = (const float*)d_in[5];
    float* out = (float*)d_out;

    float *xw_p, *h_p, *whhT_p, *wxhT_p, *woutT_p;
    cudaGetSymbolAddress((void**)&xw_p,    g_xw);
    cudaGetSymbolAddress((void**)&h_p,     g_h);
    cudaGetSymbolAddress((void**)&whhT_p,  g_WhhT);
    cudaGetSymbolAddress((void**)&wxhT_p,  g_WxhT);
    cudaGetSymbolAddress((void**)&woutT_p, g_WoutT);

    static bool attr_set = false;
    if (!attr_set) {
        cudaFuncSetAttribute(recurrence7_kernel,
                             cudaFuncAttributeMaxDynamicSharedMemorySize, SMEMB);
        attr_set = true;
    }

    // [0] transpose W_xh, [1] transpose W_hh
    transpose_kernel<<<(H_ * I_ + 255) / 256, 256>>>(W_xh, wxhT_p, H_, I_);
    transpose_kernel<<<(H_ * H_ + 255) / 256, 256>>>(W_hh, whhT_p, H_, H_);

    // [2] xw = x @ W_xh^T + b_h -> g_xw
    {
        dim3 grid((B_ * T_) / 64, H_ / 64);
        sgemm64<<<grid, 256>>>(x, wxhT_p, b_h, xw_p, B_ * T_, H_, I_);
    }

    // [3] recurrence: g_xw -> g_h
    recurrence7_kernel<<<NBG * CLN, THR, SMEMB>>>();

    // [4] transpose W_out
    transpose_kernel<<<(O_ * H_ + 255) / 256, 256>>>(W_out, woutT_p, O_, H_);

    // [5] y = h @ W_out^T + b_out
    {
        dim3 grid((B_ * T_) / 64, O_ / 64);
        sgemm64<<<grid, 256>>>(h_p, woutT_p, b_out, out, B_ * T_, O_, H_);
    }
}

// round 16
// speedup vs baseline: 2.5157x; 1.7811x over previous
#include <cuda_runtime.h>
#include <cuda_bf16.h>
#include <math.h>
#include <stdint.h>

// Problem constants
#define B_  256
#define T_  512
#define I_  128
#define H_  512
#define O_  64
#define ALPHA 0.2f
#define BETA_ 8.0f
#define THRESH 20.0f

// Recurrence decomposition: 256 CTAs = 16 batch-groups x 16 col-tiles.
// CTA: 32 cols x 16 batches, 256 threads = 32 cols x 4 quads x 2 k-halves.
#define NBG   16
#define NCT   16
#define CTW   32
#define BB    16
#define THR   256
#define KHALF 256
#define HPAD  20                    // floats per h row (80B, quads 16B-aligned)
#define WS_FLOATS (H_ * CTW)        // 16384 floats = 64KB
#define HS_FLOATS (H_ * HPAD)       // 10240 floats = 40KB
#define PS_FLOATS (128 * 4)         // 512 floats = 2KB
#define HS_OFF  WS_FLOATS
#define PS_OFF  (WS_FLOATS + HS_FLOATS)
#define SMEM_FLOATS (PS_OFF + PS_FLOATS)
#define SMEMB (SMEM_FLOATS * 4)     // 108544 B ≈ 106KB -> 2 CTAs/SM

// Scratch (device globals; no runtime allocation)
__device__ float g_xw[(size_t)B_ * T_ * H_];
__device__ float g_h [(size_t)B_ * T_ * H_];
__device__ float g_WhhT[H_ * H_];
__device__ float g_WxhT[I_ * H_];
__device__ float g_WoutT[H_ * O_];
// L2 exchange slots: [parity][bg][k][b16] (1 MB, L2-resident)
__device__ float g_hx[2][NBG][H_][BB];
__device__ int   g_cnt[NBG];

// ---------------------------------------------------------------------------
// Transpose; blockIdx.x==0 also zeroes the barrier counters (keeps launch count
// before the recurrence at 3 so ncu -s 5 lands on the recurrence).
// ---------------------------------------------------------------------------
__global__ void transpose_kernel(const float* __restrict__ in, float* __restrict__ out,
                                 int R, int C) {
    if (blockIdx.x == 0 && threadIdx.x < NBG) g_cnt[threadIdx.x] = 0;
    int idx = blockIdx.x * blockDim.x + threadIdx.x;
    if (idx < R * C) {
        int r = idx / C;
        int c = idx % C;
        out[c * R + r] = in[idx];
    }
}

// ---------------------------------------------------------------------------
// Tiled SGEMM: C[M,N] = A[M,K] * B[K,N] (+ bias[N]); 64x64 tile, BK=32.
// ---------------------------------------------------------------------------
__global__ __launch_bounds__(256) void sgemm64(const float* __restrict__ A,
                                               const float* __restrict__ Bm,
                                               const float* __restrict__ bias,
                                               float* __restrict__ C,
                                               int M, int N, int K) {
    __shared__ float As[32][65];
    __shared__ float Bs[32][64];

    int tid = threadIdx.x;
    int m0 = blockIdx.x * 64;
    int n0 = blockIdx.y * 64;
    int tx = tid % 16;
    int ty = tid / 16;

    int a_k = tid % 32;
    int a_m = tid / 32;
    int b_n = tid % 64;
    int b_k = tid / 64;

    float acc[4][4];
#pragma unroll
    for (int i = 0; i < 4; i++)
#pragma unroll
        for (int j = 0; j < 4; j++) acc[i][j] = 0.0f;

    for (int k0 = 0; k0 < K; k0 += 32) {
#pragma unroll
        for (int i = 0; i < 8; i++)
            As[a_k][a_m + 8 * i] = A[(size_t)(m0 + a_m + 8 * i) * K + (k0 + a_k)];
#pragma unroll
        for (int i = 0; i < 8; i++)
            Bs[b_k + 4 * i][b_n] = Bm[(size_t)(k0 + b_k + 4 * i) * N + (n0 + b_n)];
        __syncthreads();

#pragma unroll
        for (int kk = 0; kk < 32; kk++) {
            float a[4], b[4];
#pragma unroll
            for (int i = 0; i < 4; i++) a[i] = As[kk][ty * 4 + i];
#pragma unroll
            for (int j = 0; j < 4; j++) b[j] = Bs[kk][tx * 4 + j];
#pragma unroll
            for (int i = 0; i < 4; i++)
#pragma unroll
                for (int j = 0; j < 4; j++) acc[i][j] += a[i] * b[j];
        }
        __syncthreads();
    }

#pragma unroll
    for (int i = 0; i < 4; i++) {
        size_t row = (size_t)(m0 + ty * 4 + i);
#pragma unroll
        for (int j = 0; j < 4; j++) {
            int col = n0 + tx * 4 + j;
            float v = acc[i][j];
            if (bias) v += bias[col];
            C[row * N + col] = v;
        }
    }
}

// ---------------------------------------------------------------------------
__device__ __forceinline__ float phi_fn(float x) {
    float z = BETA_ * x;
    if (z > THRESH) return x;
    return __logf(1.0f + __expf(z)) * 0.125f;
}

__device__ __forceinline__ unsigned long long pack2(float lo, float hi) {
    unsigned long long r;
    asm("mov.b64 %0, {%1, %2};" : "=l"(r) : "r"(__float_as_uint(lo)), "r"(__float_as_uint(hi)));
    return r;
}

__device__ __forceinline__ void unpack2(unsigned long long v, float& lo, float& hi) {
    uint32_t a, b;
    asm("mov.b64 {%0, %1}, %2;" : "=r"(a), "=r"(b) : "l"(v));
    lo = __uint_as_float(a);
    hi = __uint_as_float(b);
}

__device__ __forceinline__ void fma2(unsigned long long& acc, unsigned long long h,
                                     unsigned long long w) {
    asm("fma.rn.f32x2 %0, %1, %2, %0;" : "+l"(acc) : "l"(h), "l"(w));
}

// ---------------------------------------------------------------------------
// Recurrence v8: no clusters. 256 CTAs, 2 co-resident per SM (smem 106KB) so
// one CTA's compute hides the other's barrier/restage/stall time.
// Per-bg barrier = monotonic L2 atomic counter (16 CTAs, target 16*(t+1)).
// h exchange through L2 slots (publish stcg -> barrier -> restage ldcg).
// ---------------------------------------------------------------------------
__global__ __launch_bounds__(THR, 2) void recurrence8_kernel() {
    extern __shared__ float smem[];
    float* Ws = smem;                 // [k][jl] stride 32
    float* hs = smem + HS_OFF;        // [k][b]  stride HPAD
    float* ps = smem + PS_OFF;        // [sid][4]

    const int tid = threadIdx.x;
    const int bid = blockIdx.x;
    const int bg  = bid >> 4;         // batch group 0..15
    const int ct  = bid & 15;         // col tile 0..15
    const int jl  = tid & 31;         // col within tile
    const int q   = (tid >> 5) & 3;   // batch quad 0..3
    const int kh  = tid >> 7;         // k half 0..1
    const int sid = tid & 127;        // (jl,q) id shared by the two halves
    const int jg  = ct * CTW + jl;    // global column
    const int bbase = bg * BB + q * 4;

    // ---- init: W slice (32 cols) into SMEM, zero h buffer ----
    {
        const float* __restrict__ WhhT = g_WhhT;
        const int j0 = ct * CTW;
        for (int idx = tid; idx < WS_FLOATS; idx += THR) {
            int k = idx >> 5;
            int c = idx & 31;
            Ws[idx] = WhhT[k * H_ + j0 + c];
        }
    }
    for (int idx = tid; idx < HS_FLOATS; idx += THR) hs[idx] = 0.0f;
    __syncthreads();

    const float* __restrict__ xwb = g_xw + (size_t)bbase * T_ * H_ + jg;
    float*       __restrict__ hob = g_h  + (size_t)bbase * T_ * H_ + jg;

    const int warp = tid >> 5;
    const int lane = tid & 31;
    const int stage_base = warp * 256;     // float4 index into [512][16] slot

    float hold[4];
#pragma unroll
    for (int i = 0; i < 4; i++) hold[i] = 0.0f;

    // xw for t=0 (kh==0 folds xw into its accumulators)
    float xv[4];
    if (kh == 0) {
#pragma unroll
        for (int i = 0; i < 4; i++)
            xv[i] = __ldcs(xwb + (size_t)i * T_ * H_);
    }

    volatile int* cntp = &g_cnt[bg];
    const int kbase = kh * KHALF;

    for (int t = 0; t < T_; t++) {
        const int sl = t & 1;

        // ---- partial matvec over this thread's k-half ----
        unsigned long long a0, a1;
        if (kh == 0) { a0 = pack2(xv[0], xv[1]); a1 = pack2(xv[2], xv[3]); }
        else         { a0 = 0ull;                a1 = 0ull; }

        const float* __restrict__ wp = Ws + jl;
        const float* __restrict__ hp = hs + q * 4;
#pragma unroll 8
        for (int kk = 0; kk < KHALF; kk++) {
            const int k = kbase + kk;
            float w = wp[k * CTW];                  // coalesced 128B/warp
            unsigned long long w2;
            asm("mov.b64 %0, {%1, %1};" : "=l"(w2) : "r"(__float_as_uint(w)));
            ulonglong2 hq = *reinterpret_cast<const ulonglong2*>(hp + k * HPAD); // broadcast
            fma2(a0, hq.x, w2);
            fma2(a1, hq.y, w2);
        }

        if (kh == 1) {   // publish partials to smem
            ulonglong2* pp = reinterpret_cast<ulonglong2*>(ps + (size_t)sid * 4);
            *pp = make_ulonglong2(a0, a1);
        }
        __syncthreads();

        float hn[4];
        if (kh == 0) {   // reduce + activation + L2 publish
            ulonglong2 qv = *reinterpret_cast<const ulonglong2*>(ps + (size_t)sid * 4);
            float s[4], r[4];
            unpack2(a0, s[0], s[1]); unpack2(a1, s[2], s[3]);
            unpack2(qv.x, r[0], r[1]); unpack2(qv.y, r[2], r[3]);
#pragma unroll
            for (int i = 0; i < 4; i++) {
                float pre = s[i] + r[i];
                hn[i] = (1.0f - ALPHA) * hold[i] + ALPHA * phi_fn(pre);
                hold[i] = hn[i];
            }
            __stcg(reinterpret_cast<float4*>(&g_hx[sl][bg][jg][q * 4]),
                   make_float4(hn[0], hn[1], hn[2], hn[3]));
        }
        __syncthreads();   // all publishes issued

        if (tid == 0) {    // arrive
            __threadfence();
            atomicAdd(&g_cnt[bg], 1);
        }

        // hidden work: global h stash + next xw loads
        if (kh == 0) {
#pragma unroll
            for (int i = 0; i < 4; i++)
                __stcs(hob + ((size_t)i * T_ + t) * H_, hn[i]);
            if (t < T_ - 1) {
#pragma unroll
                for (int i = 0; i < 4; i++)
                    xv[i] = __ldcs(xwb + ((size_t)i * T_ + (t + 1)) * H_);
            }
        }

        if (t < T_ - 1) {
            if (tid == 0) {   // wait for all 16 CTAs of this bg
                const int target = NCT * (t + 1);
                while (*cntp < target) __nanosleep(32);
                __threadfence();
            }
            __syncthreads();

            // ---- restage full h_t slot (32KB) from L2 into SMEM ----
            const float4* __restrict__ src =
                reinterpret_cast<const float4*>(&g_hx[sl][bg][0][0]);
            float4 v[8];
#pragma unroll
            for (int j = 0; j < 8; j++)
                v[j] = __ldcg(src + stage_base + j * 32 + lane);   // coalesced
#pragma unroll
            for (int j = 0; j < 8; j++) {
                int idx = stage_base + j * 32 + lane;
                int k   = idx >> 2;
                int bq  = idx & 3;
                *reinterpret_cast<float4*>(&hs[k * HPAD + bq * 4]) = v[j];
            }
            __syncthreads();
        }
    }
}

// ---------------------------------------------------------------------------
// kernel_launch
// inputs: x[B,T,I], W_xh[H,I], W_hh[H,H], b_h[H], W_out[O,H], b_out[O]
// output: float [B,T,O]
// ---------------------------------------------------------------------------
extern "C" void kernel_launch(void* const* d_in, const int* in_sizes, int n_in,
                              void* d_out, int out_size) {
    const float* x     = (const float*)d_in[0];
    const float* W_xh  = (const float*)d_in[1];
    const float* W_hh  = (const float*)d_in[2];
    const float* b_h   = (const float*)d_in[3];
    const float* W_out = (const float*)d_in[4];
    const float* b_out = (const float*)d_in[5];
    float* out = (float*)d_out;

    float *xw_p, *h_p, *whhT_p, *wxhT_p, *woutT_p;
    cudaGetSymbolAddress((void**)&xw_p,    g_xw);
    cudaGetSymbolAddress((void**)&h_p,     g_h);
    cudaGetSymbolAddress((void**)&whhT_p,  g_WhhT);
    cudaGetSymbolAddress((void**)&wxhT_p,  g_WxhT);
    cudaGetSymbolAddress((void**)&woutT_p, g_WoutT);

    static bool attr_set = false;
    if (!attr_set) {
        cudaFuncSetAttribute(recurrence8_kernel,
                             cudaFuncAttributeMaxDynamicSharedMemorySize, SMEMB);
        attr_set = true;
    }

    // [0] transpose W_xh (+ zero barrier counters), [1] transpose W_hh
    transpose_kernel<<<(H_ * I_ + 255) / 256, 256>>>(W_xh, wxhT_p, H_, I_);
    transpose_kernel<<<(H_ * H_ + 255) / 256, 256>>>(W_hh, whhT_p, H_, H_);

    // [2] xw = x @ W_xh^T + b_h -> g_xw
    {
        dim3 grid((B_ * T_) / 64, H_ / 64);
        sgemm64<<<grid, 256>>>(x, wxhT_p, b_h, xw_p, B_ * T_, H_, I_);
    }

    // [3] recurrence: g_xw -> g_h   (256 CTAs, 2 per SM)
    recurrence8_kernel<<<NBG * NCT, THR, SMEMB>>>();

    // [4] transpose W_out
    transpose_kernel<<<(O_ * H_ + 255) / 256, 256>>>(W_out, woutT_p, O_, H_);

    // [5] y = h @ W_out^T + b_out
    {
        dim3 grid((B_ * T_) / 64, O_ / 64);
        sgemm64<<<grid, 256>>>(h_p, woutT_p, b_out, out, B_ * T_, O_, H_);
    }
}

// round 17
// speedup vs baseline: 3.3052x; 1.3138x over previous
#include <cuda_runtime.h>
#include <cuda_bf16.h>
#include <math.h>
#include <stdint.h>

// Problem constants
#define B_  256
#define T_  512
#define I_  128
#define H_  512
#define O_  64
#define ALPHA 0.2f
#define BETA_ 8.0f
#define THRESH 20.0f

// Recurrence decomposition: 256 CTAs = 16 batch-groups x 16 col-tiles.
// CTA: 32 cols x 16 batches. Warp = 64-k slice; lane = 4 cols x 4 batches.
#define NBG   16
#define NCT   16
#define CTW   32
#define BB    16
#define THR   256
#define NKW   8                     // k-warps
#define KW    64                    // k per warp
#define WS_FLOATS (H_ * CTW)        // 16384 floats = 64KB
#define HS_FLOATS (H_ * BB)         // 8192 floats  = 32KB  ([k][b16], row 64B)
#define PS_FLOATS (NKW * 512)       // 4096 floats  = 16KB  ([kw][col*16+b])
#define HS_OFF  WS_FLOATS
#define PS_OFF  (WS_FLOATS + HS_FLOATS)
#define SMEM_FLOATS (PS_OFF + PS_FLOATS)
#define SMEMB (SMEM_FLOATS * 4)     // 114688 B = 112KB -> 2 CTAs/SM

// Scratch (device globals; no runtime allocation)
__device__ float g_xw[(size_t)B_ * T_ * H_];
__device__ float g_h [(size_t)B_ * T_ * H_];
__device__ float g_WhhT[H_ * H_];
__device__ float g_WxhT[I_ * H_];
__device__ float g_WoutT[H_ * O_];
// L2 exchange slots: [parity][bg][k][b16] (1 MB, L2-resident)
__device__ float g_hx[2][NBG][H_][BB];
__device__ int   g_cnt[NBG];

// ---------------------------------------------------------------------------
// Transpose; block 0 also zeroes the barrier counters.
// ---------------------------------------------------------------------------
__global__ void transpose_kernel(const float* __restrict__ in, float* __restrict__ out,
                                 int R, int C) {
    if (blockIdx.x == 0 && threadIdx.x < NBG) g_cnt[threadIdx.x] = 0;
    int idx = blockIdx.x * blockDim.x + threadIdx.x;
    if (idx < R * C) {
        int r = idx / C;
        int c = idx % C;
        out[c * R + r] = in[idx];
    }
}

// ---------------------------------------------------------------------------
// Tiled SGEMM: C[M,N] = A[M,K] * B[K,N] (+ bias[N]); 64x64 tile, BK=32.
// ---------------------------------------------------------------------------
__global__ __launch_bounds__(256) void sgemm64(const float* __restrict__ A,
                                               const float* __restrict__ Bm,
                                               const float* __restrict__ bias,
                                               float* __restrict__ C,
                                               int M, int N, int K) {
    __shared__ float As[32][65];
    __shared__ float Bs[32][64];

    int tid = threadIdx.x;
    int m0 = blockIdx.x * 64;
    int n0 = blockIdx.y * 64;
    int tx = tid % 16;
    int ty = tid / 16;

    int a_k = tid % 32;
    int a_m = tid / 32;
    int b_n = tid % 64;
    int b_k = tid / 64;

    float acc[4][4];
#pragma unroll
    for (int i = 0; i < 4; i++)
#pragma unroll
        for (int j = 0; j < 4; j++) acc[i][j] = 0.0f;

    for (int k0 = 0; k0 < K; k0 += 32) {
#pragma unroll
        for (int i = 0; i < 8; i++)
            As[a_k][a_m + 8 * i] = A[(size_t)(m0 + a_m + 8 * i) * K + (k0 + a_k)];
#pragma unroll
        for (int i = 0; i < 8; i++)
            Bs[b_k + 4 * i][b_n] = Bm[(size_t)(k0 + b_k + 4 * i) * N + (n0 + b_n)];
        __syncthreads();

#pragma unroll
        for (int kk = 0; kk < 32; kk++) {
            float a[4], b[4];
#pragma unroll
            for (int i = 0; i < 4; i++) a[i] = As[kk][ty * 4 + i];
#pragma unroll
            for (int j = 0; j < 4; j++) b[j] = Bs[kk][tx * 4 + j];
#pragma unroll
            for (int i = 0; i < 4; i++)
#pragma unroll
                for (int j = 0; j < 4; j++) acc[i][j] += a[i] * b[j];
        }
        __syncthreads();
    }

#pragma unroll
    for (int i = 0; i < 4; i++) {
        size_t row = (size_t)(m0 + ty * 4 + i);
#pragma unroll
        for (int j = 0; j < 4; j++) {
            int col = n0 + tx * 4 + j;
            float v = acc[i][j];
            if (bias) v += bias[col];
            C[row * N + col] = v;
        }
    }
}

// ---------------------------------------------------------------------------
__device__ __forceinline__ float phi_fn(float x) {
    float z = BETA_ * x;
    if (z > THRESH) return x;
    return __logf(1.0f + __expf(z)) * 0.125f;
}

__device__ __forceinline__ uint32_t smem_u32(const void* p) {
    uint32_t a;
    asm("{ .reg .u64 t; cvta.to.shared.u64 t, %1; cvt.u32.u64 %0, t; }" : "=r"(a) : "l"(p));
    return a;
}

__device__ __forceinline__ unsigned long long pack2(float lo, float hi) {
    unsigned long long r;
    asm("mov.b64 %0, {%1, %2};" : "=l"(r) : "r"(__float_as_uint(lo)), "r"(__float_as_uint(hi)));
    return r;
}

__device__ __forceinline__ unsigned long long dup2(float v) {
    unsigned long long r;
    asm("mov.b64 %0, {%1, %1};" : "=l"(r) : "r"(__float_as_uint(v)));
    return r;
}

__device__ __forceinline__ void fma2(unsigned long long& acc, unsigned long long h,
                                     unsigned long long w) {
    asm("fma.rn.f32x2 %0, %1, %2, %0;" : "+l"(acc) : "l"(h), "l"(w));
}

__device__ __forceinline__ void cp_async16(uint32_t saddr, const void* gaddr) {
    asm volatile("cp.async.cg.shared.global [%0], [%1], 16;"
                 :: "r"(saddr), "l"(gaddr) : "memory");
}

// ---------------------------------------------------------------------------
// Recurrence v9: 256 CTAs, 2/SM. Warp = 64-k slice over the full 32x16 tile;
// lane tile = 4 cols x 4 batches (32 MACs per 2 LDS.128). Smem partial reduce,
// L2 h-exchange, per-bg atomic barrier, per-warp cp.async restage.
// ---------------------------------------------------------------------------
__global__ __launch_bounds__(THR, 2) void recurrence9_kernel() {
    extern __shared__ float smem[];
    float* Ws = smem;                 // [k][jl] stride 32
    float* hs = smem + HS_OFF;        // [k][b]  stride 16
    float* ps = smem + PS_OFF;        // [kw][col*16 + b]

    const int tid  = threadIdx.x;
    const int bid  = blockIdx.x;
    const int bg   = bid >> 4;        // batch group 0..15
    const int ct   = bid & 15;        // col tile 0..15
    const int warp = tid >> 5;        // k-slice 0..7
    const int lane = tid & 31;
    const int c    = lane & 7;        // col group: cols 4c..4c+3
    const int bqi  = lane >> 3;       // batch group: batches 4bqi..4bqi+3

    // reduce-role: thread owns (col_r, batches br, br+1)
    const int col_r = tid >> 3;            // 0..31
    const int br    = (tid & 7) * 2;       // 0,2,..,14
    const int jg_r  = ct * CTW + col_r;    // global column for reduce outputs

    // ---- init: W slice into SMEM, zero h buffer ----
    {
        const float* __restrict__ WhhT = g_WhhT;
        const int j0 = ct * CTW;
        for (int idx = tid; idx < WS_FLOATS; idx += THR) {
            int k = idx >> 5;
            int cc = idx & 31;
            Ws[idx] = WhhT[k * H_ + j0 + cc];
        }
    }
    for (int idx = tid; idx < HS_FLOATS; idx += THR) hs[idx] = 0.0f;
    __syncthreads();

    // reduce-role global pointers (batch br, br+1 of this bg)
    const float* __restrict__ xwb = g_xw + (size_t)(bg * BB + br) * T_ * H_ + jg_r;
    float*       __restrict__ hob = g_h  + (size_t)(bg * BB + br) * T_ * H_ + jg_r;
    const size_t bstr = (size_t)T_ * H_;   // batch stride

    float hold0 = 0.0f, hold1 = 0.0f;
    float xv0 = __ldcs(xwb);
    float xv1 = __ldcs(xwb + bstr);

    volatile int* cntp = &g_cnt[bg];
    const uint32_t hs_u32 = smem_u32(hs);

    const float* wrow0 = Ws + (size_t)warp * KW * CTW + c * 4;
    const float* hrow0 = hs + (size_t)warp * KW * BB + bqi * 4;
    float* pbase = ps + warp * 512 + (c * 4) * 16 + bqi * 4;   // [col*16+b]
    const float* prd = ps + col_r * 16 + br;

    for (int t = 0; t < T_; t++) {
        const int sl = t & 1;

        // ---- k-loop: 64 k, 4 cols x 4 batches per lane ----
        unsigned long long acc[4][2];
#pragma unroll
        for (int i = 0; i < 4; i++) { acc[i][0] = 0ull; acc[i][1] = 0ull; }

        const float4* wr = reinterpret_cast<const float4*>(wrow0);
        const float4* hr = reinterpret_cast<const float4*>(hrow0);
#pragma unroll 8
        for (int kk = 0; kk < KW; kk++) {
            float4 w4 = wr[0]; wr += CTW / 4;    // next k row (32 floats)
            float4 h4 = hr[0]; hr += BB / 4;     // next k row (16 floats)
            unsigned long long h01 = pack2(h4.x, h4.y);
            unsigned long long h23 = pack2(h4.z, h4.w);
            unsigned long long w2;
            w2 = dup2(w4.x); fma2(acc[0][0], h01, w2); fma2(acc[0][1], h23, w2);
            w2 = dup2(w4.y); fma2(acc[1][0], h01, w2); fma2(acc[1][1], h23, w2);
            w2 = dup2(w4.z); fma2(acc[2][0], h01, w2); fma2(acc[2][1], h23, w2);
            w2 = dup2(w4.w); fma2(acc[3][0], h01, w2); fma2(acc[3][1], h23, w2);
        }

        // ---- store partials: ps[warp][(4c+cc)*16 + 4bqi .. +3] ----
#pragma unroll
        for (int cc = 0; cc < 4; cc++) {
            *reinterpret_cast<ulonglong2*>(pbase + cc * 16) =
                make_ulonglong2(acc[cc][0], acc[cc][1]);
        }
        __syncthreads();   // #1: partials visible

        // ---- reduce + activation + publish (each thread: col_r, br, br+1) ----
        float s0 = xv0, s1 = xv1;
#pragma unroll
        for (int w = 0; w < NKW; w++) {
            float2 v = *reinterpret_cast<const float2*>(prd + w * 512);
            s0 += v.x; s1 += v.y;
        }
        float hn0 = (1.0f - ALPHA) * hold0 + ALPHA * phi_fn(s0); hold0 = hn0;
        float hn1 = (1.0f - ALPHA) * hold1 + ALPHA * phi_fn(s1); hold1 = hn1;

        __stcg(reinterpret_cast<float2*>(&g_hx[sl][bg][jg_r][br]),
               make_float2(hn0, hn1));
        __syncthreads();   // #2: all publishes issued

        if (t < T_ - 1) {
            if (tid == 0) {            // arrive
                __threadfence();
                atomicAdd(&g_cnt[bg], 1);
            }
            // hidden under the barrier: h stash + next xw loads
            __stcs(hob + (size_t)t * H_, hn0);
            __stcs(hob + bstr + (size_t)t * H_, hn1);
            xv0 = __ldcs(xwb + (size_t)(t + 1) * H_);
            xv1 = __ldcs(xwb + bstr + (size_t)(t + 1) * H_);

            if (tid == 0) {            // wait for all 16 CTAs of this bg
                const int target = NCT * (t + 1);
                while (*cntp < target) __nanosleep(16);
                __threadfence();
            }
            __syncthreads();           // #3: h_t slot complete in L2

            // ---- per-warp restage of OWN 64 h-rows via cp.async ----
            const float4* src = reinterpret_cast<const float4*>(&g_hx[sl][bg][0][0]);
            const int base4 = warp * 256;                 // float4 index
#pragma unroll
            for (int j = 0; j < 8; j++) {
                int idx4 = base4 + j * 32 + lane;
                cp_async16(hs_u32 + (uint32_t)idx4 * 16u, src + idx4);
            }
            asm volatile("cp.async.commit_group;" ::: "memory");
            asm volatile("cp.async.wait_group 0;" ::: "memory");
            __syncwarp();
        } else {
            __stcs(hob + (size_t)t * H_, hn0);
            __stcs(hob + bstr + (size_t)t * H_, hn1);
        }
    }
}

// ---------------------------------------------------------------------------
// kernel_launch
// inputs: x[B,T,I], W_xh[H,I], W_hh[H,H], b_h[H], W_out[O,H], b_out[O]
// output: float [B,T,O]
// ---------------------------------------------------------------------------
extern "C" void kernel_launch(void* const* d_in, const int* in_sizes, int n_in,
                              void* d_out, int out_size) {
    const float* x     = (const float*)d_in[0];
    const float* W_xh  = (const float*)d_in[1];
    const float* W_hh  = (const float*)d_in[2];
    const float* b_h   = (const float*)d_in[3];
    const float* W_out = (const float*)d_in[4];
    const float* b_out = (const float*)d_in[5];
    float* out = (float*)d_out;

    float *xw_p, *h_p, *whhT_p, *wxhT_p, *woutT_p;
    cudaGetSymbolAddress((void**)&xw_p,    g_xw);
    cudaGetSymbolAddress((void**)&h_p,     g_h);
    cudaGetSymbolAddress((void**)&whhT_p,  g_WhhT);
    cudaGetSymbolAddress((void**)&wxhT_p,  g_WxhT);
    cudaGetSymbolAddress((void**)&woutT_p, g_WoutT);

    static bool attr_set = false;
    if (!attr_set) {
        cudaFuncSetAttribute(recurrence9_kernel,
                             cudaFuncAttributeMaxDynamicSharedMemorySize, SMEMB);
        attr_set = true;
    }

    // [0] transpose W_xh (+ zero barrier counters), [1] transpose W_hh
    transpose_kernel<<<(H_ * I_ + 255) / 256, 256>>>(W_xh, wxhT_p, H_, I_);
    transpose_kernel<<<(H_ * H_ + 255) / 256, 256>>>(W_hh, whhT_p, H_, H_);

    // [2] xw = x @ W_xh^T + b_h -> g_xw
    {
        dim3 grid((B_ * T_) / 64, H_ / 64);
        sgemm64<<<grid, 256>>>(x, wxhT_p, b_h, xw_p, B_ * T_, H_, I_);
    }

    // [3] recurrence: g_xw -> g_h   (256 CTAs, 2 per SM)
    recurrence9_kernel<<<NBG * NCT, THR, SMEMB>>>();

    // [4] transpose W_out
    transpose_kernel<<<(O_ * H_ + 255) / 256, 256>>>(W_out, woutT_p, O_, H_);

    // [5] y = h @ W_out^T + b_out
    {
        dim3 grid((B_ * T_) / 64, O_ / 64);
        sgemm64<<<grid, 256>>>(h_p, woutT_p, b_out, out, B_ * T_, O_, H_);
    }
}